// round 15
// baseline (speedup 1.0000x reference)
#include <cuda_runtime.h>
#include <cuda_bf16.h>
#include <math.h>
#include <stdint.h>

#define D 256
#define BATCH 64
#define NTOK 4096
#define S 8
#define ROWS_BIG (BATCH * NTOK)   // 262144
#define ROWS_SLOT (BATCH * S)     // 512
#define PRED 8                    // partials per batch after in-CTA reduce

// ---------------- scratch (device globals; no allocations allowed) ----------
__device__ __nv_bfloat16 g_xln16[(size_t)ROWS_BIG * D];    // 134 MB
__device__ __nv_bfloat16 g_kv16[(size_t)ROWS_BIG * 2 * D]; // 268 MB, row=[k|v]
__device__ __nv_bfloat16 g_w16[2 * D * D];                 // concat(Wk, Wv) [512,256]
__device__ float g_bias[2 * D];                            // concat(bk, bv)
__device__ float g_slots[ROWS_SLOT * D];
__device__ float g_qbuf[ROWS_SLOT * D];
__device__ float g_upd[ROWS_SLOT * D];
__device__ float g_hbuf[ROWS_SLOT * D];
__device__ float g_gx[ROWS_SLOT * 3 * D];
__device__ float g_gh[ROWS_SLOT * 3 * D];
__device__ float g_pnum[(size_t)BATCH * PRED * S * D];     // 4.2 MB
__device__ float g_pden[BATCH * PRED * S];

// ---------------- PTX helpers (arch-agnostic features only) ------------------
__device__ __forceinline__ uint32_t smem_u32(const void* p) {
    uint32_t a;
    asm("{ .reg .u64 t; cvta.to.shared.u64 t, %1; cvt.u32.u64 %0, t; }" : "=r"(a) : "l"(p));
    return a;
}
__device__ __forceinline__ void cpasync16(uint32_t saddr, const void* g) {
    asm volatile("cp.async.cg.shared.global [%0], [%1], 16;" :: "r"(saddr), "l"(g));
}
#define CP_COMMIT() asm volatile("cp.async.commit_group;" ::: "memory")
#define CP_WAIT(n)  asm volatile("cp.async.wait_group %0;" :: "n"(n) : "memory")

__device__ __forceinline__ void ldsm_x4(uint32_t& r0, uint32_t& r1, uint32_t& r2, uint32_t& r3,
                                        uint32_t addr) {
    asm volatile("ldmatrix.sync.aligned.m8n8.x4.shared.b16 {%0,%1,%2,%3}, [%4];"
                 : "=r"(r0), "=r"(r1), "=r"(r2), "=r"(r3) : "r"(addr));
}
__device__ __forceinline__ void mma16816(float* d, const uint32_t* a, const uint32_t* b) {
    asm volatile("mma.sync.aligned.m16n8k16.row.col.f32.bf16.bf16.f32 "
                 "{%0,%1,%2,%3}, {%4,%5,%6,%7}, {%8,%9}, {%0,%1,%2,%3};"
                 : "+f"(d[0]), "+f"(d[1]), "+f"(d[2]), "+f"(d[3])
                 : "r"(a[0]), "r"(a[1]), "r"(a[2]), "r"(a[3]), "r"(b[0]), "r"(b[1]));
}
__device__ __forceinline__ float2 bf2f(uint32_t u) {
    __nv_bfloat162 h = *reinterpret_cast<__nv_bfloat162*>(&u);
    return __bfloat1622float2(h);
}
// packed f32x2 (base PTX, sm_100+, no arch-specific suffix)
#define PACKF2(out, lo, hi) asm("mov.b64 %0, {%1, %2};" : "=l"(out) : "f"(lo), "f"(hi))
#define UNPACKF2(lo, hi, in) asm("mov.b64 {%0, %1}, %2;" : "=f"(lo), "=f"(hi) : "l"(in))
#define MUL2(d, a, b)    asm("mul.rn.f32x2 %0, %1, %2;" : "=l"(d) : "l"(a), "l"(b))
#define FMA2(d, a, b, c) asm("fma.rn.f32x2 %0, %1, %2, %3;" : "=l"(d) : "l"(a), "l"(b), "l"(c))

// ---------------- weights fp32 -> bf16 (concat layout) -----------------------
__global__ void conv_w_kernel(const float* __restrict__ wk, const float* __restrict__ wv,
                              const float* __restrict__ bk, const float* __restrict__ bv,
                              __nv_bfloat16* __restrict__ w16, float* __restrict__ bias)
{
    int i = blockIdx.x * 256 + threadIdx.x;   // 0..65535
    w16[i]             = __float2bfloat16(wk[i]);
    w16[i + D * D]     = __float2bfloat16(wv[i]);
    if (i < D) { bias[i] = bk[i]; bias[i + D] = bv[i]; }
}

// ---------------- LayerNorm fp32 -> bf16 (big input) -------------------------
__global__ void ln_rows_bf16_kernel(const float* __restrict__ in, __nv_bfloat16* __restrict__ out,
                                    const float* __restrict__ gamma, const float* __restrict__ beta)
{
    int gw   = (blockIdx.x * blockDim.x + threadIdx.x) >> 5;
    int lane = threadIdx.x & 31;
    const float* row = in + (size_t)gw * D;
    float4 a = *(const float4*)(row + lane * 4);
    float4 b = *(const float4*)(row + 128 + lane * 4);
    float s  = a.x + a.y + a.z + a.w + b.x + b.y + b.z + b.w;
    float s2 = a.x*a.x + a.y*a.y + a.z*a.z + a.w*a.w
             + b.x*b.x + b.y*b.y + b.z*b.z + b.w*b.w;
#pragma unroll
    for (int off = 16; off; off >>= 1) {
        s  += __shfl_xor_sync(0xffffffffu, s,  off);
        s2 += __shfl_xor_sync(0xffffffffu, s2, off);
    }
    float mean = s * (1.0f / 256.0f);
    float var  = s2 * (1.0f / 256.0f) - mean * mean;
    float rstd = rsqrtf(var + 1e-5f);
    float4 g0 = *(const float4*)(gamma + lane * 4);
    float4 g1 = *(const float4*)(gamma + 128 + lane * 4);
    float4 e0 = *(const float4*)(beta + lane * 4);
    float4 e1 = *(const float4*)(beta + 128 + lane * 4);
    __nv_bfloat162 p[4];
    p[0] = __float22bfloat162_rn(make_float2((a.x - mean) * rstd * g0.x + e0.x,
                                             (a.y - mean) * rstd * g0.y + e0.y));
    p[1] = __float22bfloat162_rn(make_float2((a.z - mean) * rstd * g0.z + e0.z,
                                             (a.w - mean) * rstd * g0.w + e0.w));
    p[2] = __float22bfloat162_rn(make_float2((b.x - mean) * rstd * g1.x + e1.x,
                                             (b.y - mean) * rstd * g1.y + e1.y));
    p[3] = __float22bfloat162_rn(make_float2((b.z - mean) * rstd * g1.z + e1.z,
                                             (b.w - mean) * rstd * g1.w + e1.w));
    __nv_bfloat16* o = out + (size_t)gw * D;
    *(uint2*)(o + lane * 4)       = make_uint2(*(uint32_t*)&p[0], *(uint32_t*)&p[1]);
    *(uint2*)(o + 128 + lane * 4) = make_uint2(*(uint32_t*)&p[2], *(uint32_t*)&p[3]);
}

// ---------------- KV projection: bf16 mma.sync GEMM --------------------------
// C row = [k(256) | v(256)] interleaved, row stride 512 bf16.
// __launch_bounds__(256, 2): cap regs at 128 so 2 CTAs/SM co-reside and hide
// the pipeline sync bubbles (tested in isolation this round).
#define BMT 128
#define BNT 128
#define KV_STAGE 16384
#define KV_SMEM  (4 * KV_STAGE)        // 64 KB

__global__ void __launch_bounds__(256, 2) kv_mma_kernel(
    const __nv_bfloat16* __restrict__ A,
    const __nv_bfloat16* __restrict__ W,
    const float* __restrict__ bias,
    __nv_bfloat16* __restrict__ KV)
{
    extern __shared__ char smem[];
    const int tid  = threadIdx.x;
    const int lane = tid & 31;
    const int wid  = tid >> 5;
    const int wm   = wid >> 1;
    const int wn   = wid & 1;
    const int bm   = blockIdx.y * BMT;
    const int bn   = blockIdx.x * BNT;
    const uint32_t sb = smem_u32(smem);

    const char* Ag = (const char*)A + (size_t)bm * 512;
    const char* Wg = (const char*)W + (size_t)bn * 512;

    float acc[2][8][4];
#pragma unroll
    for (int mi = 0; mi < 2; mi++)
#pragma unroll
        for (int nj = 0; nj < 8; nj++)
#pragma unroll
            for (int x = 0; x < 4; x++) acc[mi][nj][x] = 0.0f;

#define LOAD_STAGE(kb, st) do {                                               \
        uint32_t abase = sb + (st) * 2 * KV_STAGE;                            \
        uint32_t bbase = abase + KV_STAGE;                                    \
        const char* ag = Ag + (kb) * 128;                                     \
        const char* wg = Wg + (kb) * 128;                                     \
        _Pragma("unroll")                                                     \
        for (int i = 0; i < 4; i++) {                                         \
            int ci = tid + i * 256;                                           \
            int r = ci >> 3, c = ci & 7;                                      \
            cpasync16(abase + r * 128 + ((c ^ (r & 7)) * 16),                 \
                      ag + (size_t)r * 512 + c * 16);                         \
        }                                                                     \
        _Pragma("unroll")                                                     \
        for (int i = 0; i < 4; i++) {                                         \
            int ci = tid + i * 256;                                           \
            int r = ci >> 3, c = ci & 7;                                      \
            cpasync16(bbase + r * 128 + ((c ^ (r & 7)) * 16),                 \
                      wg + (size_t)r * 512 + c * 16);                         \
        }                                                                     \
        CP_COMMIT();                                                          \
    } while (0)

    LOAD_STAGE(0, 0);

#pragma unroll 1
    for (int kb = 0; kb < 4; kb++) {
        if (kb < 3) { LOAD_STAGE(kb + 1, (kb + 1) & 1); CP_WAIT(1); }
        else        { CP_WAIT(0); }
        __syncthreads();

        uint32_t abase = sb + (kb & 1) * 2 * KV_STAGE;
        uint32_t bbase = abase + KV_STAGE;
#pragma unroll
        for (int ks = 0; ks < 4; ks++) {
            uint32_t afr[2][4];
#pragma unroll
            for (int mi = 0; mi < 2; mi++) {
                int row   = wm * 32 + mi * 16 + (lane & 15);
                int chunk = (ks * 2 + (lane >> 4)) ^ (row & 7);
                ldsm_x4(afr[mi][0], afr[mi][1], afr[mi][2], afr[mi][3],
                        abase + row * 128 + chunk * 16);
            }
            uint32_t bfr[8][2];
#pragma unroll
            for (int njp = 0; njp < 4; njp++) {
                int row   = wn * 64 + njp * 16 + ((lane >> 4) & 1) * 8 + (lane & 7);
                int chunk = (ks * 2 + ((lane >> 3) & 1)) ^ (row & 7);
                uint32_t r0, r1, r2, r3;
                ldsm_x4(r0, r1, r2, r3, bbase + row * 128 + chunk * 16);
                bfr[njp * 2][0]     = r0; bfr[njp * 2][1]     = r1;
                bfr[njp * 2 + 1][0] = r2; bfr[njp * 2 + 1][1] = r3;
            }
#pragma unroll
            for (int mi = 0; mi < 2; mi++)
#pragma unroll
                for (int nj = 0; nj < 8; nj++)
                    mma16816(acc[mi][nj], afr[mi], bfr[nj]);
        }
        __syncthreads();
    }

    // epilogue: interleaved KV output (row stride 512, col = bn + ncol)
#pragma unroll
    for (int mi = 0; mi < 2; mi++) {
        int r0 = bm + wm * 32 + mi * 16 + (lane >> 2);
#pragma unroll
        for (int nj = 0; nj < 8; nj++) {
            int ncol = wn * 64 + nj * 8 + (lane & 3) * 2;
            float2 bs = *(const float2*)&bias[bn + ncol];
            __nv_bfloat162 lo = __float22bfloat162_rn(
                make_float2(acc[mi][nj][0] + bs.x, acc[mi][nj][1] + bs.y));
            __nv_bfloat162 hi = __float22bfloat162_rn(
                make_float2(acc[mi][nj][2] + bs.x, acc[mi][nj][3] + bs.y));
            *(__nv_bfloat162*)(KV + (size_t)r0 * 512 + bn + ncol)       = lo;
            *(__nv_bfloat162*)(KV + (size_t)(r0 + 8) * 512 + bn + ncol) = hi;
        }
    }
#undef LOAD_STAGE
}

// ---------------- Small fp32 SGEMM (optionally two problems in one grid) -----
template <int BM, int BN, int BK, int TM, int TN>
__global__ void sgemm_kernel(const float* __restrict__ A, const float* __restrict__ W,
                             const float* __restrict__ bias, float* __restrict__ C,
                             int M, int N, int K, int relu, int accum,
                             const float* __restrict__ A2, const float* __restrict__ W2,
                             const float* __restrict__ bias2, float* __restrict__ C2,
                             int halfx)
{
    constexpr int THREADS = (BM / TM) * (BN / TN);
    __shared__ float As[BK][BM + 4];
    __shared__ float Ws[BK][BN + 4];
    const int tid  = threadIdx.x;
    int bxn = blockIdx.x;
    const float* Au = A; const float* Wu = W; const float* bu = bias; float* Cu = C;
    if (bxn >= halfx) {
        bxn -= halfx; Au = A2; Wu = W2; bu = bias2; Cu = C2;
    }
    const int bm   = blockIdx.y * BM;
    const int bn   = bxn * BN;
    const int tcol = (tid % (BN / TN)) * TN;
    const int trow = (tid / (BN / TN)) * TM;

    float acc[TM][TN];
#pragma unroll
    for (int i = 0; i < TM; i++)
#pragma unroll
        for (int j = 0; j < TN; j++) acc[i][j] = 0.0f;

    for (int k0 = 0; k0 < K; k0 += BK) {
        constexpr int AL = (BM * BK) / (THREADS * 4);
#pragma unroll
        for (int t = 0; t < AL; t++) {
            int idx = (tid + t * THREADS) * 4;
            int r = idx / BK, c = idx % BK;
            float4 val = *(const float4*)&Au[(size_t)(bm + r) * K + k0 + c];
            As[c + 0][r] = val.x; As[c + 1][r] = val.y;
            As[c + 2][r] = val.z; As[c + 3][r] = val.w;
        }
        constexpr int WL = (BN * BK) / (THREADS * 4);
#pragma unroll
        for (int t = 0; t < WL; t++) {
            int idx = (tid + t * THREADS) * 4;
            int r = idx / BK, c = idx % BK;
            float4 val = *(const float4*)&Wu[(size_t)(bn + r) * K + k0 + c];
            Ws[c + 0][r] = val.x; Ws[c + 1][r] = val.y;
            Ws[c + 2][r] = val.z; Ws[c + 3][r] = val.w;
        }
        __syncthreads();
#pragma unroll
        for (int kk = 0; kk < BK; kk++) {
            float a[TM], b[TN];
#pragma unroll
            for (int i = 0; i < TM; i += 4) {
                float4 t4 = *(const float4*)&As[kk][trow + i];
                a[i] = t4.x; a[i + 1] = t4.y; a[i + 2] = t4.z; a[i + 3] = t4.w;
            }
#pragma unroll
            for (int j = 0; j < TN; j += 4) {
                float4 t4 = *(const float4*)&Ws[kk][tcol + j];
                b[j] = t4.x; b[j + 1] = t4.y; b[j + 2] = t4.z; b[j + 3] = t4.w;
            }
#pragma unroll
            for (int i = 0; i < TM; i++)
#pragma unroll
                for (int j = 0; j < TN; j++) acc[i][j] += a[i] * b[j];
        }
        __syncthreads();
    }

#pragma unroll
    for (int i = 0; i < TM; i++) {
        int r = bm + trow + i;
#pragma unroll
        for (int j = 0; j < TN; j += 4) {
            int c = bn + tcol + j;
            float4 o;
            o.x = acc[i][j + 0] + bu[c + 0];
            o.y = acc[i][j + 1] + bu[c + 1];
            o.z = acc[i][j + 2] + bu[c + 2];
            o.w = acc[i][j + 3] + bu[c + 3];
            if (relu) {
                o.x = fmaxf(o.x, 0.0f); o.y = fmaxf(o.y, 0.0f);
                o.z = fmaxf(o.z, 0.0f); o.w = fmaxf(o.w, 0.0f);
            }
            if (accum) {
                float4 old = *(const float4*)&Cu[(size_t)r * N + c];
                o.x += old.x; o.y += old.y; o.z += old.z; o.w += old.w;
            }
            *(float4*)&Cu[(size_t)r * N + c] = o;
        }
    }
}

// ---------------- slotgemm v3: 32x64 tile, K resident, LN fused, f32x2 -------
#define SG_SMEM ((32 * 260 + 256 * 68) * 4)    // 102912 B

template <int RELU>
__global__ void __launch_bounds__(256) slotgemm_ln_kernel(
    const float* __restrict__ A, const float* __restrict__ W,
    const float* __restrict__ bias, float* __restrict__ C,
    const float* __restrict__ gamma, const float* __restrict__ beta)
{
    extern __shared__ float sm[];
    float* Af = sm;               // [32][260]
    float* Ws = sm + 32 * 260;    // [256][68] k-major
    const int tid = threadIdx.x;
    const int bm = blockIdx.y * 32;
    const int bn = blockIdx.x * 64;

#pragma unroll
    for (int t = 0; t < 16; t++) {
        int e = tid + t * 256;
        int row = e >> 6;
        int kc  = (e & 63) * 4;
        float4 wv = *(const float4*)&W[(size_t)(bn + row) * D + kc];
        Ws[(kc + 0) * 68 + row] = wv.x; Ws[(kc + 1) * 68 + row] = wv.y;
        Ws[(kc + 2) * 68 + row] = wv.z; Ws[(kc + 3) * 68 + row] = wv.w;
    }

    {
        const int wid = tid >> 5, lane = tid & 31;
        float4 g0 = *(const float4*)(gamma + lane * 4);
        float4 g1 = *(const float4*)(gamma + 128 + lane * 4);
        float4 e0 = *(const float4*)(beta + lane * 4);
        float4 e1 = *(const float4*)(beta + 128 + lane * 4);
#pragma unroll 1
        for (int j = 0; j < 4; j++) {
            int lr = wid * 4 + j;
            const float* row = A + (size_t)(bm + lr) * D;
            float4 a = *(const float4*)(row + lane * 4);
            float4 c = *(const float4*)(row + 128 + lane * 4);
            float s  = a.x + a.y + a.z + a.w + c.x + c.y + c.z + c.w;
            float s2 = a.x*a.x + a.y*a.y + a.z*a.z + a.w*a.w
                     + c.x*c.x + c.y*c.y + c.z*c.z + c.w*c.w;
#pragma unroll
            for (int off = 16; off; off >>= 1) {
                s  += __shfl_xor_sync(0xffffffffu, s,  off);
                s2 += __shfl_xor_sync(0xffffffffu, s2, off);
            }
            float mean = s * (1.0f / 256.0f);
            float rstd = rsqrtf(s2 * (1.0f / 256.0f) - mean * mean + 1e-5f);
            float4 o0, o1;
            o0.x = (a.x - mean) * rstd * g0.x + e0.x;
            o0.y = (a.y - mean) * rstd * g0.y + e0.y;
            o0.z = (a.z - mean) * rstd * g0.z + e0.z;
            o0.w = (a.w - mean) * rstd * g0.w + e0.w;
            o1.x = (c.x - mean) * rstd * g1.x + e1.x;
            o1.y = (c.y - mean) * rstd * g1.y + e1.y;
            o1.z = (c.z - mean) * rstd * g1.z + e1.z;
            o1.w = (c.w - mean) * rstd * g1.w + e1.w;
            *(float4*)&Af[lr * 260 + lane * 4]       = o0;
            *(float4*)&Af[lr * 260 + 128 + lane * 4] = o1;
        }
    }
    __syncthreads();

    const int trow = (tid >> 4) * 2;
    const int tcol = (tid & 15) * 4;
    unsigned long long acc2[2][2];
    acc2[0][0] = 0ULL; acc2[0][1] = 0ULL; acc2[1][0] = 0ULL; acc2[1][1] = 0ULL;

#pragma unroll 2
    for (int k4 = 0; k4 < D; k4 += 4) {
        float4 av0 = *(const float4*)&Af[trow * 260 + k4];
        float4 av1 = *(const float4*)&Af[(trow + 1) * 260 + k4];
#pragma unroll
        for (int j = 0; j < 4; j++) {
            ulonglong2 bv = *(const ulonglong2*)&Ws[(k4 + j) * 68 + tcol];
            float a0 = j == 0 ? av0.x : j == 1 ? av0.y : j == 2 ? av0.z : av0.w;
            float a1 = j == 0 ? av1.x : j == 1 ? av1.y : j == 2 ? av1.z : av1.w;
            unsigned long long p0, p1;
            PACKF2(p0, a0, a0);
            PACKF2(p1, a1, a1);
            FMA2(acc2[0][0], p0, bv.x, acc2[0][0]);
            FMA2(acc2[0][1], p0, bv.y, acc2[0][1]);
            FMA2(acc2[1][0], p1, bv.x, acc2[1][0]);
            FMA2(acc2[1][1], p1, bv.y, acc2[1][1]);
        }
    }

#pragma unroll
    for (int i = 0; i < 2; i++) {
        int r = bm + trow + i;
        int c = bn + tcol;
        float c0, c1, c2, c3;
        UNPACKF2(c0, c1, acc2[i][0]);
        UNPACKF2(c2, c3, acc2[i][1]);
        float4 bsv = *(const float4*)&bias[c];
        float4 o;
        o.x = c0 + bsv.x; o.y = c1 + bsv.y; o.z = c2 + bsv.z; o.w = c3 + bsv.w;
        if (RELU) {
            o.x = fmaxf(o.x, 0.0f); o.y = fmaxf(o.y, 0.0f);
            o.z = fmaxf(o.z, 0.0f); o.w = fmaxf(o.w, 0.0f);
        }
        *(float4*)&C[(size_t)r * D + c] = o;
    }
}

// ---------------- Fused attention pass (interleaved KV, contiguous stream) ---
__global__ void __launch_bounds__(256) attn_pass_kernel(
    const float* __restrict__ q,
    const __nv_bfloat16* __restrict__ kv,
    float* __restrict__ pnum,
    float* __restrict__ pden)
{
    extern __shared__ float sred[];          // 8*2048 floats + 64 den
    const int b    = blockIdx.y;
    const int wid  = threadIdx.x >> 5;
    const int lane = threadIdx.x & 31;
    const int tid  = threadIdx.x;
    const int wg   = blockIdx.x * 8 + wid;   // 0..63
    const float scale = 0.0625f;

    unsigned long long qp[8][4];
    const float* qb = q + b * S * D;
#pragma unroll
    for (int i = 0; i < 8; i++) {
        float4 q0 = *(const float4*)(qb + i * D + lane * 8);
        float4 q1 = *(const float4*)(qb + i * D + lane * 8 + 4);
        PACKF2(qp[i][0], q0.x * scale, q0.y * scale);
        PACKF2(qp[i][1], q0.z * scale, q0.w * scale);
        PACKF2(qp[i][2], q1.x * scale, q1.y * scale);
        PACKF2(qp[i][3], q1.z * scale, q1.w * scale);
    }

    unsigned long long acc2[8][4];
#pragma unroll
    for (int i = 0; i < 8; i++)
#pragma unroll
        for (int j = 0; j < 4; j++) acc2[i][j] = 0ULL;
    float den[8] = {0, 0, 0, 0, 0, 0, 0, 0};

    // warp's contiguous token block: [wg*64, wg*64+64)
    const __nv_bfloat16* kvb = kv + ((size_t)b * NTOK + (size_t)wg * 64) * 512;

    const __nv_bfloat16* p0 = kvb + lane * 8;
    uint4 ku = *(const uint4*)(p0);
    uint4 vu = *(const uint4*)(p0 + 256);

#pragma unroll 1
    for (int t = 0; t < 64; t++) {
        uint4 nku = ku, nvu = vu;
        if (t < 63) {
            const __nv_bfloat16* pn = kvb + (size_t)(t + 1) * 512 + lane * 8;
            nku = *(const uint4*)(pn);
            nvu = *(const uint4*)(pn + 256);
        }

        unsigned long long kp[4];
        { float2 f;
          f = bf2f(ku.x); PACKF2(kp[0], f.x, f.y);
          f = bf2f(ku.y); PACKF2(kp[1], f.x, f.y);
          f = bf2f(ku.z); PACKF2(kp[2], f.x, f.y);
          f = bf2f(ku.w); PACKF2(kp[3], f.x, f.y); }

        float dot[8];
#pragma unroll
        for (int i = 0; i < 8; i++) {
            unsigned long long t2;
            MUL2(t2, qp[i][0], kp[0]);
            FMA2(t2, qp[i][1], kp[1], t2);
            FMA2(t2, qp[i][2], kp[2], t2);
            FMA2(t2, qp[i][3], kp[3], t2);
            float lo, hi; UNPACKF2(lo, hi, t2);
            dot[i] = lo + hi;
        }
#pragma unroll
        for (int off = 16; off; off >>= 1)
#pragma unroll
            for (int i = 0; i < 8; i++)
                dot[i] += __shfl_xor_sync(0xffffffffu, dot[i], off);

        float e[8]; float ssum = 0.0f;
#pragma unroll
        for (int i = 0; i < 8; i++) { e[i] = exp2f(dot[i] * 1.44269504f); ssum += e[i]; }
        float inv = 1.0f / ssum;

        unsigned long long vp[4];
        { float2 f;
          f = bf2f(vu.x); PACKF2(vp[0], f.x, f.y);
          f = bf2f(vu.y); PACKF2(vp[1], f.x, f.y);
          f = bf2f(vu.z); PACKF2(vp[2], f.x, f.y);
          f = bf2f(vu.w); PACKF2(vp[3], f.x, f.y); }
#pragma unroll
        for (int i = 0; i < 8; i++) {
            float a = e[i] * inv + 1e-8f;
            den[i] += a;
            unsigned long long aa; PACKF2(aa, a, a);
            FMA2(acc2[i][0], aa, vp[0], acc2[i][0]);
            FMA2(acc2[i][1], aa, vp[1], acc2[i][1]);
            FMA2(acc2[i][2], aa, vp[2], acc2[i][2]);
            FMA2(acc2[i][3], aa, vp[3], acc2[i][3]);
        }

        ku = nku; vu = nvu;
    }

    float* sA = sred;
    float* sD = sred + 8 * 2048;
#pragma unroll
    for (int i = 0; i < 8; i++) {
        float a0, a1, a2, a3, a4, a5, a6, a7;
        UNPACKF2(a0, a1, acc2[i][0]); UNPACKF2(a2, a3, acc2[i][1]);
        UNPACKF2(a4, a5, acc2[i][2]); UNPACKF2(a6, a7, acc2[i][3]);
        *(float4*)(sA + wid * 2048 + i * 256 + lane * 8)     = make_float4(a0, a1, a2, a3);
        *(float4*)(sA + wid * 2048 + i * 256 + lane * 8 + 4) = make_float4(a4, a5, a6, a7);
    }
    if (lane == 0) {
#pragma unroll
        for (int i = 0; i < 8; i++) sD[wid * 8 + i] = den[i];
    }
    __syncthreads();

    float* pn = pnum + ((size_t)b * PRED + blockIdx.x) * S * D;
#pragma unroll
    for (int r = 0; r < 8; r++) {
        int idx = tid + r * 256;
        float s = 0.0f;
#pragma unroll
        for (int w = 0; w < 8; w++) s += sA[w * 2048 + idx];
        pn[idx] = s;
    }
    if (tid < 8) {
        float s = 0.0f;
#pragma unroll
        for (int w = 0; w < 8; w++) s += sD[w * 8 + tid];
        pden[(b * PRED + blockIdx.x) * S + tid] = s;
    }
}

__global__ void attn_reduce_kernel(const float* __restrict__ pnum,
                                   const float* __restrict__ pden,
                                   float* __restrict__ upd)
{
    int idx = blockIdx.x * blockDim.x + threadIdx.x;  // over 64*2048
    int b = idx >> 11;
    int i = (idx >> 8) & 7;
    float s = 0.0f, d = 0.0f;
#pragma unroll
    for (int w = 0; w < PRED; w++) {
        s += pnum[((size_t)b * PRED + w) * S * D + (idx & 2047)];
        d += pden[(b * PRED + w) * S + i];
    }
    upd[idx] = s / d;
}

// ---------------- GRU pointwise (torch gate order r,z,n) ---------------------
__global__ void gru_kernel(const float* __restrict__ gx, const float* __restrict__ gh,
                           float* __restrict__ slots)
{
    int idx = blockIdx.x * blockDim.x + threadIdx.x;  // over 512*256
    int row = idx >> 8, d = idx & 255;
    const float* gxr = gx + row * 3 * D;
    const float* ghr = gh + row * 3 * D;
    float xr = gxr[d], xz = gxr[D + d], xn = gxr[2 * D + d];
    float hr = ghr[d], hz = ghr[D + d], hn = ghr[2 * D + d];
    float r = 1.0f / (1.0f + expf(-(xr + hr)));
    float z = 1.0f / (1.0f + expf(-(xz + hz)));
    float nv = tanhf(xn + r * hn);
    float prev = slots[idx];
    slots[idx] = (1.0f - z) * nv + z * prev;
}

// ---------------- host orchestration ----------------------------------------
extern "C" void kernel_launch(void* const* d_in, const int* in_sizes, int n_in,
                              void* d_out, int out_size)
{
    const float* inputs     = (const float*)d_in[0];
    const float* init_slots = (const float*)d_in[1];
    const float* wq   = (const float*)d_in[2];  const float* bq   = (const float*)d_in[3];
    const float* wk   = (const float*)d_in[4];  const float* bk   = (const float*)d_in[5];
    const float* wv   = (const float*)d_in[6];  const float* bv   = (const float*)d_in[7];
    const float* w_ih = (const float*)d_in[8];  const float* b_ih = (const float*)d_in[9];
    const float* w_hh = (const float*)d_in[10]; const float* b_hh = (const float*)d_in[11];
    const float* w1   = (const float*)d_in[12]; const float* b1   = (const float*)d_in[13];
    const float* w2   = (const float*)d_in[14]; const float* b2   = (const float*)d_in[15];
    const float* gin  = (const float*)d_in[16]; const float* bin  = (const float*)d_in[17];
    const float* gsl  = (const float*)d_in[18]; const float* bsl  = (const float*)d_in[19];
    const float* gff  = (const float*)d_in[20]; const float* bff  = (const float*)d_in[21];

    __nv_bfloat16 *xln16, *kv16, *w16;
    float *bias, *slots, *qb, *upd, *hb, *gx, *gh, *pnum, *pden;
    cudaGetSymbolAddress((void**)&xln16, g_xln16);
    cudaGetSymbolAddress((void**)&kv16,  g_kv16);
    cudaGetSymbolAddress((void**)&w16,   g_w16);
    cudaGetSymbolAddress((void**)&bias,  g_bias);
    cudaGetSymbolAddress((void**)&slots, g_slots);
    cudaGetSymbolAddress((void**)&qb,    g_qbuf);
    cudaGetSymbolAddress((void**)&upd,   g_upd);
    cudaGetSymbolAddress((void**)&hb,    g_hbuf);
    cudaGetSymbolAddress((void**)&gx,    g_gx);
    cudaGetSymbolAddress((void**)&gh,    g_gh);
    cudaGetSymbolAddress((void**)&pnum,  g_pnum);
    cudaGetSymbolAddress((void**)&pden,  g_pden);

    cudaFuncSetAttribute(kv_mma_kernel, cudaFuncAttributeMaxDynamicSharedMemorySize, KV_SMEM);
    const int ATTN_SMEM = (8 * 2048 + 64) * sizeof(float);
    cudaFuncSetAttribute(attn_pass_kernel, cudaFuncAttributeMaxDynamicSharedMemorySize, ATTN_SMEM);
    cudaFuncSetAttribute(slotgemm_ln_kernel<0>, cudaFuncAttributeMaxDynamicSharedMemorySize, SG_SMEM);
    cudaFuncSetAttribute(slotgemm_ln_kernel<1>, cudaFuncAttributeMaxDynamicSharedMemorySize, SG_SMEM);

    // prologue
    cudaMemcpyAsync(slots, init_slots, (size_t)ROWS_SLOT * D * sizeof(float),
                    cudaMemcpyDeviceToDevice);
    conv_w_kernel<<<D * D / 256, 256>>>(wk, wv, bk, bv, w16, bias);
    ln_rows_bf16_kernel<<<ROWS_BIG / 8, 256>>>(inputs, xln16, gin, bin);
    kv_mma_kernel<<<dim3(4, ROWS_BIG / BMT), 256, KV_SMEM>>>(xln16, w16, bias, kv16);

    for (int it = 0; it < 3; it++) {
        // q = LN(slots) @ wq^T + bq
        slotgemm_ln_kernel<0><<<dim3(4, 16), 256, SG_SMEM>>>(
            slots, wq, bq, qb, gsl, bsl);
        attn_pass_kernel<<<dim3(PRED, BATCH), 256, ATTN_SMEM>>>(qb, kv16, pnum, pden);
        attn_reduce_kernel<<<(BATCH * S * D) / 256, 256>>>(pnum, pden, upd);
        // gx and gh GEMMs in one launch
        sgemm_kernel<64, 64, 16, 4, 4><<<dim3(24, 8), 256>>>(
            upd, w_ih, b_ih, gx, ROWS_SLOT, 3 * D, D, 0, 0,
            slots, w_hh, b_hh, gh, 12);
        gru_kernel<<<(ROWS_SLOT * D) / 256, 256>>>(gx, gh, slots);
        // h = relu(LN(slots) @ w1^T + b1)
        slotgemm_ln_kernel<1><<<dim3(4, 16), 256, SG_SMEM>>>(
            slots, w1, b1, hb, gff, bff);
        // slots += h @ w2^T + b2
        sgemm_kernel<64, 64, 16, 4, 4><<<dim3(4, 8), 256>>>(
            hb, w2, b2, slots, ROWS_SLOT, D, D, 0, 1,
            nullptr, nullptr, nullptr, nullptr, 1 << 20);
    }

    cudaMemcpyAsync(d_out, slots, (size_t)ROWS_SLOT * D * sizeof(float),
                    cudaMemcpyDeviceToDevice);
}

// round 16
// speedup vs baseline: 1.0177x; 1.0177x over previous
#include <cuda_runtime.h>
#include <cuda_bf16.h>
#include <math.h>
#include <stdint.h>

#define D 256
#define BATCH 64
#define NTOK 4096
#define S 8
#define ROWS_BIG (BATCH * NTOK)   // 262144
#define ROWS_SLOT (BATCH * S)     // 512
#define PRED 8                    // partials per batch after in-CTA reduce

// ---------------- scratch (device globals; no allocations allowed) ----------
__device__ __nv_bfloat16 g_xln16[(size_t)ROWS_BIG * D];    // 134 MB
__device__ __nv_bfloat16 g_kv16[(size_t)ROWS_BIG * 2 * D]; // 268 MB, row=[k|v]
__device__ __nv_bfloat16 g_w16[2 * D * D];                 // concat(Wk, Wv) [512,256]
__device__ float g_bias[2 * D];                            // concat(bk, bv)
__device__ float g_slots[ROWS_SLOT * D];
__device__ float g_qbuf[ROWS_SLOT * D];
__device__ float g_upd[ROWS_SLOT * D];
__device__ float g_hbuf[ROWS_SLOT * D];
__device__ float g_gx[ROWS_SLOT * 3 * D];
__device__ float g_gh[ROWS_SLOT * 3 * D];
__device__ float g_pnum[(size_t)BATCH * PRED * S * D];     // 4.2 MB
__device__ float g_pden[BATCH * PRED * S];

// ---------------- PTX helpers (arch-agnostic features only) ------------------
__device__ __forceinline__ uint32_t smem_u32(const void* p) {
    uint32_t a;
    asm("{ .reg .u64 t; cvta.to.shared.u64 t, %1; cvt.u32.u64 %0, t; }" : "=r"(a) : "l"(p));
    return a;
}
__device__ __forceinline__ void cpasync16(uint32_t saddr, const void* g) {
    asm volatile("cp.async.cg.shared.global [%0], [%1], 16;" :: "r"(saddr), "l"(g));
}
#define CP_COMMIT() asm volatile("cp.async.commit_group;" ::: "memory")
#define CP_WAIT(n)  asm volatile("cp.async.wait_group %0;" :: "n"(n) : "memory")

__device__ __forceinline__ void ldsm_x4(uint32_t& r0, uint32_t& r1, uint32_t& r2, uint32_t& r3,
                                        uint32_t addr) {
    asm volatile("ldmatrix.sync.aligned.m8n8.x4.shared.b16 {%0,%1,%2,%3}, [%4];"
                 : "=r"(r0), "=r"(r1), "=r"(r2), "=r"(r3) : "r"(addr));
}
__device__ __forceinline__ void mma16816(float* d, const uint32_t* a, const uint32_t* b) {
    asm volatile("mma.sync.aligned.m16n8k16.row.col.f32.bf16.bf16.f32 "
                 "{%0,%1,%2,%3}, {%4,%5,%6,%7}, {%8,%9}, {%0,%1,%2,%3};"
                 : "+f"(d[0]), "+f"(d[1]), "+f"(d[2]), "+f"(d[3])
                 : "r"(a[0]), "r"(a[1]), "r"(a[2]), "r"(a[3]), "r"(b[0]), "r"(b[1]));
}
__device__ __forceinline__ float2 bf2f(uint32_t u) {
    __nv_bfloat162 h = *reinterpret_cast<__nv_bfloat162*>(&u);
    return __bfloat1622float2(h);
}
// packed f32x2 (base PTX, sm_100+, no arch-specific suffix)
#define PACKF2(out, lo, hi) asm("mov.b64 %0, {%1, %2};" : "=l"(out) : "f"(lo), "f"(hi))
#define UNPACKF2(lo, hi, in) asm("mov.b64 {%0, %1}, %2;" : "=f"(lo), "=f"(hi) : "l"(in))
#define MUL2(d, a, b)    asm("mul.rn.f32x2 %0, %1, %2;" : "=l"(d) : "l"(a), "l"(b))
#define FMA2(d, a, b, c) asm("fma.rn.f32x2 %0, %1, %2, %3;" : "=l"(d) : "l"(a), "l"(b), "l"(c))

// ---------------- weights fp32 -> bf16 (concat layout) -----------------------
__global__ void conv_w_kernel(const float* __restrict__ wk, const float* __restrict__ wv,
                              const float* __restrict__ bk, const float* __restrict__ bv,
                              __nv_bfloat16* __restrict__ w16, float* __restrict__ bias)
{
    int i = blockIdx.x * 256 + threadIdx.x;   // 0..65535
    w16[i]             = __float2bfloat16(wk[i]);
    w16[i + D * D]     = __float2bfloat16(wv[i]);
    if (i < D) { bias[i] = bk[i]; bias[i + D] = bv[i]; }
}

// ---------------- LayerNorm fp32 -> bf16 (big input) -------------------------
__global__ void ln_rows_bf16_kernel(const float* __restrict__ in, __nv_bfloat16* __restrict__ out,
                                    const float* __restrict__ gamma, const float* __restrict__ beta)
{
    int gw   = (blockIdx.x * blockDim.x + threadIdx.x) >> 5;
    int lane = threadIdx.x & 31;
    const float* row = in + (size_t)gw * D;
    float4 a = *(const float4*)(row + lane * 4);
    float4 b = *(const float4*)(row + 128 + lane * 4);
    float s  = a.x + a.y + a.z + a.w + b.x + b.y + b.z + b.w;
    float s2 = a.x*a.x + a.y*a.y + a.z*a.z + a.w*a.w
             + b.x*b.x + b.y*b.y + b.z*b.z + b.w*b.w;
#pragma unroll
    for (int off = 16; off; off >>= 1) {
        s  += __shfl_xor_sync(0xffffffffu, s,  off);
        s2 += __shfl_xor_sync(0xffffffffu, s2, off);
    }
    float mean = s * (1.0f / 256.0f);
    float var  = s2 * (1.0f / 256.0f) - mean * mean;
    float rstd = rsqrtf(var + 1e-5f);
    float4 g0 = *(const float4*)(gamma + lane * 4);
    float4 g1 = *(const float4*)(gamma + 128 + lane * 4);
    float4 e0 = *(const float4*)(beta + lane * 4);
    float4 e1 = *(const float4*)(beta + 128 + lane * 4);
    __nv_bfloat162 p[4];
    p[0] = __float22bfloat162_rn(make_float2((a.x - mean) * rstd * g0.x + e0.x,
                                             (a.y - mean) * rstd * g0.y + e0.y));
    p[1] = __float22bfloat162_rn(make_float2((a.z - mean) * rstd * g0.z + e0.z,
                                             (a.w - mean) * rstd * g0.w + e0.w));
    p[2] = __float22bfloat162_rn(make_float2((b.x - mean) * rstd * g1.x + e1.x,
                                             (b.y - mean) * rstd * g1.y + e1.y));
    p[3] = __float22bfloat162_rn(make_float2((b.z - mean) * rstd * g1.z + e1.z,
                                             (b.w - mean) * rstd * g1.w + e1.w));
    __nv_bfloat16* o = out + (size_t)gw * D;
    *(uint2*)(o + lane * 4)       = make_uint2(*(uint32_t*)&p[0], *(uint32_t*)&p[1]);
    *(uint2*)(o + 128 + lane * 4) = make_uint2(*(uint32_t*)&p[2], *(uint32_t*)&p[3]);
}

// ---------------- KV projection: bf16 mma.sync GEMM (R13 exact) --------------
// C row = [k(256) | v(256)] interleaved, row stride 512 bf16.
// No min-blocks cap: R15 isolation test showed (256,2) is -6us (neutral/worse).
#define BMT 128
#define BNT 128
#define KV_STAGE 16384
#define KV_SMEM  (4 * KV_STAGE)        // 64 KB

__global__ void __launch_bounds__(256) kv_mma_kernel(
    const __nv_bfloat16* __restrict__ A,
    const __nv_bfloat16* __restrict__ W,
    const float* __restrict__ bias,
    __nv_bfloat16* __restrict__ KV)
{
    extern __shared__ char smem[];
    const int tid  = threadIdx.x;
    const int lane = tid & 31;
    const int wid  = tid >> 5;
    const int wm   = wid >> 1;
    const int wn   = wid & 1;
    const int bm   = blockIdx.y * BMT;
    const int bn   = blockIdx.x * BNT;
    const uint32_t sb = smem_u32(smem);

    const char* Ag = (const char*)A + (size_t)bm * 512;
    const char* Wg = (const char*)W + (size_t)bn * 512;

    float acc[2][8][4];
#pragma unroll
    for (int mi = 0; mi < 2; mi++)
#pragma unroll
        for (int nj = 0; nj < 8; nj++)
#pragma unroll
            for (int x = 0; x < 4; x++) acc[mi][nj][x] = 0.0f;

#define LOAD_STAGE(kb, st) do {                                               \
        uint32_t abase = sb + (st) * 2 * KV_STAGE;                            \
        uint32_t bbase = abase + KV_STAGE;                                    \
        const char* ag = Ag + (kb) * 128;                                     \
        const char* wg = Wg + (kb) * 128;                                     \
        _Pragma("unroll")                                                     \
        for (int i = 0; i < 4; i++) {                                         \
            int ci = tid + i * 256;                                           \
            int r = ci >> 3, c = ci & 7;                                      \
            cpasync16(abase + r * 128 + ((c ^ (r & 7)) * 16),                 \
                      ag + (size_t)r * 512 + c * 16);                         \
        }                                                                     \
        _Pragma("unroll")                                                     \
        for (int i = 0; i < 4; i++) {                                         \
            int ci = tid + i * 256;                                           \
            int r = ci >> 3, c = ci & 7;                                      \
            cpasync16(bbase + r * 128 + ((c ^ (r & 7)) * 16),                 \
                      wg + (size_t)r * 512 + c * 16);                         \
        }                                                                     \
        CP_COMMIT();                                                          \
    } while (0)

    LOAD_STAGE(0, 0);

#pragma unroll 1
    for (int kb = 0; kb < 4; kb++) {
        if (kb < 3) { LOAD_STAGE(kb + 1, (kb + 1) & 1); CP_WAIT(1); }
        else        { CP_WAIT(0); }
        __syncthreads();

        uint32_t abase = sb + (kb & 1) * 2 * KV_STAGE;
        uint32_t bbase = abase + KV_STAGE;
#pragma unroll
        for (int ks = 0; ks < 4; ks++) {
            uint32_t afr[2][4];
#pragma unroll
            for (int mi = 0; mi < 2; mi++) {
                int row   = wm * 32 + mi * 16 + (lane & 15);
                int chunk = (ks * 2 + (lane >> 4)) ^ (row & 7);
                ldsm_x4(afr[mi][0], afr[mi][1], afr[mi][2], afr[mi][3],
                        abase + row * 128 + chunk * 16);
            }
            uint32_t bfr[8][2];
#pragma unroll
            for (int njp = 0; njp < 4; njp++) {
                int row   = wn * 64 + njp * 16 + ((lane >> 4) & 1) * 8 + (lane & 7);
                int chunk = (ks * 2 + ((lane >> 3) & 1)) ^ (row & 7);
                uint32_t r0, r1, r2, r3;
                ldsm_x4(r0, r1, r2, r3, bbase + row * 128 + chunk * 16);
                bfr[njp * 2][0]     = r0; bfr[njp * 2][1]     = r1;
                bfr[njp * 2 + 1][0] = r2; bfr[njp * 2 + 1][1] = r3;
            }
#pragma unroll
            for (int mi = 0; mi < 2; mi++)
#pragma unroll
                for (int nj = 0; nj < 8; nj++)
                    mma16816(acc[mi][nj], afr[mi], bfr[nj]);
        }
        __syncthreads();
    }

    // epilogue: interleaved KV output (row stride 512, col = bn + ncol)
#pragma unroll
    for (int mi = 0; mi < 2; mi++) {
        int r0 = bm + wm * 32 + mi * 16 + (lane >> 2);
#pragma unroll
        for (int nj = 0; nj < 8; nj++) {
            int ncol = wn * 64 + nj * 8 + (lane & 3) * 2;
            float2 bs = *(const float2*)&bias[bn + ncol];
            __nv_bfloat162 lo = __float22bfloat162_rn(
                make_float2(acc[mi][nj][0] + bs.x, acc[mi][nj][1] + bs.y));
            __nv_bfloat162 hi = __float22bfloat162_rn(
                make_float2(acc[mi][nj][2] + bs.x, acc[mi][nj][3] + bs.y));
            *(__nv_bfloat162*)(KV + (size_t)r0 * 512 + bn + ncol)       = lo;
            *(__nv_bfloat162*)(KV + (size_t)(r0 + 8) * 512 + bn + ncol) = hi;
        }
    }
#undef LOAD_STAGE
}

// ---------------- Small fp32 SGEMM (optionally two problems in one grid) -----
template <int BM, int BN, int BK, int TM, int TN>
__global__ void sgemm_kernel(const float* __restrict__ A, const float* __restrict__ W,
                             const float* __restrict__ bias, float* __restrict__ C,
                             int M, int N, int K, int relu, int accum,
                             const float* __restrict__ A2, const float* __restrict__ W2,
                             const float* __restrict__ bias2, float* __restrict__ C2,
                             int halfx)
{
    constexpr int THREADS = (BM / TM) * (BN / TN);
    __shared__ float As[BK][BM + 4];
    __shared__ float Ws[BK][BN + 4];
    const int tid  = threadIdx.x;
    int bxn = blockIdx.x;
    const float* Au = A; const float* Wu = W; const float* bu = bias; float* Cu = C;
    if (bxn >= halfx) {
        bxn -= halfx; Au = A2; Wu = W2; bu = bias2; Cu = C2;
    }
    const int bm   = blockIdx.y * BM;
    const int bn   = bxn * BN;
    const int tcol = (tid % (BN / TN)) * TN;
    const int trow = (tid / (BN / TN)) * TM;

    float acc[TM][TN];
#pragma unroll
    for (int i = 0; i < TM; i++)
#pragma unroll
        for (int j = 0; j < TN; j++) acc[i][j] = 0.0f;

    for (int k0 = 0; k0 < K; k0 += BK) {
        constexpr int AL = (BM * BK) / (THREADS * 4);
#pragma unroll
        for (int t = 0; t < AL; t++) {
            int idx = (tid + t * THREADS) * 4;
            int r = idx / BK, c = idx % BK;
            float4 val = *(const float4*)&Au[(size_t)(bm + r) * K + k0 + c];
            As[c + 0][r] = val.x; As[c + 1][r] = val.y;
            As[c + 2][r] = val.z; As[c + 3][r] = val.w;
        }
        constexpr int WL = (BN * BK) / (THREADS * 4);
#pragma unroll
        for (int t = 0; t < WL; t++) {
            int idx = (tid + t * THREADS) * 4;
            int r = idx / BK, c = idx % BK;
            float4 val = *(const float4*)&Wu[(size_t)(bn + r) * K + k0 + c];
            Ws[c + 0][r] = val.x; Ws[c + 1][r] = val.y;
            Ws[c + 2][r] = val.z; Ws[c + 3][r] = val.w;
        }
        __syncthreads();
#pragma unroll
        for (int kk = 0; kk < BK; kk++) {
            float a[TM], b[TN];
#pragma unroll
            for (int i = 0; i < TM; i += 4) {
                float4 t4 = *(const float4*)&As[kk][trow + i];
                a[i] = t4.x; a[i + 1] = t4.y; a[i + 2] = t4.z; a[i + 3] = t4.w;
            }
#pragma unroll
            for (int j = 0; j < TN; j += 4) {
                float4 t4 = *(const float4*)&Ws[kk][tcol + j];
                b[j] = t4.x; b[j + 1] = t4.y; b[j + 2] = t4.z; b[j + 3] = t4.w;
            }
#pragma unroll
            for (int i = 0; i < TM; i++)
#pragma unroll
                for (int j = 0; j < TN; j++) acc[i][j] += a[i] * b[j];
        }
        __syncthreads();
    }

#pragma unroll
    for (int i = 0; i < TM; i++) {
        int r = bm + trow + i;
#pragma unroll
        for (int j = 0; j < TN; j += 4) {
            int c = bn + tcol + j;
            float4 o;
            o.x = acc[i][j + 0] + bu[c + 0];
            o.y = acc[i][j + 1] + bu[c + 1];
            o.z = acc[i][j + 2] + bu[c + 2];
            o.w = acc[i][j + 3] + bu[c + 3];
            if (relu) {
                o.x = fmaxf(o.x, 0.0f); o.y = fmaxf(o.y, 0.0f);
                o.z = fmaxf(o.z, 0.0f); o.w = fmaxf(o.w, 0.0f);
            }
            if (accum) {
                float4 old = *(const float4*)&Cu[(size_t)r * N + c];
                o.x += old.x; o.y += old.y; o.z += old.z; o.w += old.w;
            }
            *(float4*)&Cu[(size_t)r * N + c] = o;
        }
    }
}

// ---------------- slotgemm v3.1: conflict-free W staging ---------------------
// C[512, N] = LN(A)[512,256] @ W[N,256]^T + bias (+relu).  BM=32, BN=64.
// Grid (N/64, 16).  W staged k-major [256][68]; the staging decomposition is
// col = e&63 / kc = (e>>6)*4 so scalar STS are lane-consecutive (the previous
// mapping had lane-stride 272 floats -> 16-way bank conflicts, measured as a
// 13us staging tax).  LDG becomes 32-sector/warp but W is L2-resident.
#define SG_SMEM ((32 * 260 + 256 * 68) * 4)    // 102912 B

template <int RELU>
__global__ void __launch_bounds__(256) slotgemm_ln_kernel(
    const float* __restrict__ A, const float* __restrict__ W,
    const float* __restrict__ bias, float* __restrict__ C,
    const float* __restrict__ gamma, const float* __restrict__ beta)
{
    extern __shared__ float sm[];
    float* Af = sm;               // [32][260]
    float* Ws = sm + 32 * 260;    // [256][68] k-major
    const int tid = threadIdx.x;
    const int bm = blockIdx.y * 32;
    const int bn = blockIdx.x * 64;

    // stage W transposed: conflict-free STS (lane-consecutive cols)
#pragma unroll
    for (int t = 0; t < 16; t++) {
        int e   = tid + t * 256;         // 0..4095
        int col = e & 63;                // out-col 0..63 (lane-consecutive)
        int kc  = (e >> 6) * 4;          // k group 0,4,...,252
        float4 wv = *(const float4*)&W[(size_t)(bn + col) * D + kc];
        Ws[(kc + 0) * 68 + col] = wv.x; Ws[(kc + 1) * 68 + col] = wv.y;
        Ws[(kc + 2) * 68 + col] = wv.z; Ws[(kc + 3) * 68 + col] = wv.w;
    }

    // stage A slab (32 rows), LN'd: warp w does rows w*4..w*4+3
    {
        const int wid = tid >> 5, lane = tid & 31;
        float4 g0 = *(const float4*)(gamma + lane * 4);
        float4 g1 = *(const float4*)(gamma + 128 + lane * 4);
        float4 e0 = *(const float4*)(beta + lane * 4);
        float4 e1 = *(const float4*)(beta + 128 + lane * 4);
#pragma unroll 1
        for (int j = 0; j < 4; j++) {
            int lr = wid * 4 + j;
            const float* row = A + (size_t)(bm + lr) * D;
            float4 a = *(const float4*)(row + lane * 4);
            float4 c = *(const float4*)(row + 128 + lane * 4);
            float s  = a.x + a.y + a.z + a.w + c.x + c.y + c.z + c.w;
            float s2 = a.x*a.x + a.y*a.y + a.z*a.z + a.w*a.w
                     + c.x*c.x + c.y*c.y + c.z*c.z + c.w*c.w;
#pragma unroll
            for (int off = 16; off; off >>= 1) {
                s  += __shfl_xor_sync(0xffffffffu, s,  off);
                s2 += __shfl_xor_sync(0xffffffffu, s2, off);
            }
            float mean = s * (1.0f / 256.0f);
            float rstd = rsqrtf(s2 * (1.0f / 256.0f) - mean * mean + 1e-5f);
            float4 o0, o1;
            o0.x = (a.x - mean) * rstd * g0.x + e0.x;
            o0.y = (a.y - mean) * rstd * g0.y + e0.y;
            o0.z = (a.z - mean) * rstd * g0.z + e0.z;
            o0.w = (a.w - mean) * rstd * g0.w + e0.w;
            o1.x = (c.x - mean) * rstd * g1.x + e1.x;
            o1.y = (c.y - mean) * rstd * g1.y + e1.y;
            o1.z = (c.z - mean) * rstd * g1.z + e1.z;
            o1.w = (c.w - mean) * rstd * g1.w + e1.w;
            *(float4*)&Af[lr * 260 + lane * 4]       = o0;
            *(float4*)&Af[lr * 260 + 128 + lane * 4] = o1;
        }
    }
    __syncthreads();

    // mainloop: TM=2, TN=4, f32x2 FMA, no syncs (unchanged, conflict-free)
    const int trow = (tid >> 4) * 2;
    const int tcol = (tid & 15) * 4;
    unsigned long long acc2[2][2];
    acc2[0][0] = 0ULL; acc2[0][1] = 0ULL; acc2[1][0] = 0ULL; acc2[1][1] = 0ULL;

#pragma unroll 2
    for (int k4 = 0; k4 < D; k4 += 4) {
        float4 av0 = *(const float4*)&Af[trow * 260 + k4];
        float4 av1 = *(const float4*)&Af[(trow + 1) * 260 + k4];
#pragma unroll
        for (int j = 0; j < 4; j++) {
            ulonglong2 bv = *(const ulonglong2*)&Ws[(k4 + j) * 68 + tcol];
            float a0 = j == 0 ? av0.x : j == 1 ? av0.y : j == 2 ? av0.z : av0.w;
            float a1 = j == 0 ? av1.x : j == 1 ? av1.y : j == 2 ? av1.z : av1.w;
            unsigned long long p0, p1;
            PACKF2(p0, a0, a0);
            PACKF2(p1, a1, a1);
            FMA2(acc2[0][0], p0, bv.x, acc2[0][0]);
            FMA2(acc2[0][1], p0, bv.y, acc2[0][1]);
            FMA2(acc2[1][0], p1, bv.x, acc2[1][0]);
            FMA2(acc2[1][1], p1, bv.y, acc2[1][1]);
        }
    }

#pragma unroll
    for (int i = 0; i < 2; i++) {
        int r = bm + trow + i;
        int c = bn + tcol;
        float c0, c1, c2, c3;
        UNPACKF2(c0, c1, acc2[i][0]);
        UNPACKF2(c2, c3, acc2[i][1]);
        float4 bsv = *(const float4*)&bias[c];
        float4 o;
        o.x = c0 + bsv.x; o.y = c1 + bsv.y; o.z = c2 + bsv.z; o.w = c3 + bsv.w;
        if (RELU) {
            o.x = fmaxf(o.x, 0.0f); o.y = fmaxf(o.y, 0.0f);
            o.z = fmaxf(o.z, 0.0f); o.w = fmaxf(o.w, 0.0f);
        }
        *(float4*)&C[(size_t)r * D + c] = o;
    }
}

// ---------------- Fused attention pass (interleaved KV, contiguous stream) ---
__global__ void __launch_bounds__(256) attn_pass_kernel(
    const float* __restrict__ q,
    const __nv_bfloat16* __restrict__ kv,
    float* __restrict__ pnum,
    float* __restrict__ pden)
{
    extern __shared__ float sred[];          // 8*2048 floats + 64 den
    const int b    = blockIdx.y;
    const int wid  = threadIdx.x >> 5;
    const int lane = threadIdx.x & 31;
    const int tid  = threadIdx.x;
    const int wg   = blockIdx.x * 8 + wid;   // 0..63
    const float scale = 0.0625f;

    unsigned long long qp[8][4];
    const float* qb = q + b * S * D;
#pragma unroll
    for (int i = 0; i < 8; i++) {
        float4 q0 = *(const float4*)(qb + i * D + lane * 8);
        float4 q1 = *(const float4*)(qb + i * D + lane * 8 + 4);
        PACKF2(qp[i][0], q0.x * scale, q0.y * scale);
        PACKF2(qp[i][1], q0.z * scale, q0.w * scale);
        PACKF2(qp[i][2], q1.x * scale, q1.y * scale);
        PACKF2(qp[i][3], q1.z * scale, q1.w * scale);
    }

    unsigned long long acc2[8][4];
#pragma unroll
    for (int i = 0; i < 8; i++)
#pragma unroll
        for (int j = 0; j < 4; j++) acc2[i][j] = 0ULL;
    float den[8] = {0, 0, 0, 0, 0, 0, 0, 0};

    // warp's contiguous token block: [wg*64, wg*64+64)
    const __nv_bfloat16* kvb = kv + ((size_t)b * NTOK + (size_t)wg * 64) * 512;

    const __nv_bfloat16* p0 = kvb + lane * 8;
    uint4 ku = *(const uint4*)(p0);
    uint4 vu = *(const uint4*)(p0 + 256);

#pragma unroll 1
    for (int t = 0; t < 64; t++) {
        uint4 nku = ku, nvu = vu;
        if (t < 63) {
            const __nv_bfloat16* pn = kvb + (size_t)(t + 1) * 512 + lane * 8;
            nku = *(const uint4*)(pn);
            nvu = *(const uint4*)(pn + 256);
        }

        unsigned long long kp[4];
        { float2 f;
          f = bf2f(ku.x); PACKF2(kp[0], f.x, f.y);
          f = bf2f(ku.y); PACKF2(kp[1], f.x, f.y);
          f = bf2f(ku.z); PACKF2(kp[2], f.x, f.y);
          f = bf2f(ku.w); PACKF2(kp[3], f.x, f.y); }

        float dot[8];
#pragma unroll
        for (int i = 0; i < 8; i++) {
            unsigned long long t2;
            MUL2(t2, qp[i][0], kp[0]);
            FMA2(t2, qp[i][1], kp[1], t2);
            FMA2(t2, qp[i][2], kp[2], t2);
            FMA2(t2, qp[i][3], kp[3], t2);
            float lo, hi; UNPACKF2(lo, hi, t2);
            dot[i] = lo + hi;
        }
#pragma unroll
        for (int off = 16; off; off >>= 1)
#pragma unroll
            for (int i = 0; i < 8; i++)
                dot[i] += __shfl_xor_sync(0xffffffffu, dot[i], off);

        float e[8]; float ssum = 0.0f;
#pragma unroll
        for (int i = 0; i < 8; i++) { e[i] = exp2f(dot[i] * 1.44269504f); ssum += e[i]; }
        float inv = 1.0f / ssum;

        unsigned long long vp[4];
        { float2 f;
          f = bf2f(vu.x); PACKF2(vp[0], f.x, f.y);
          f = bf2f(vu.y); PACKF2(vp[1], f.x, f.y);
          f = bf2f(vu.z); PACKF2(vp[2], f.x, f.y);
          f = bf2f(vu.w); PACKF2(vp[3], f.x, f.y); }
#pragma unroll
        for (int i = 0; i < 8; i++) {
            float a = e[i] * inv + 1e-8f;
            den[i] += a;
            unsigned long long aa; PACKF2(aa, a, a);
            FMA2(acc2[i][0], aa, vp[0], acc2[i][0]);
            FMA2(acc2[i][1], aa, vp[1], acc2[i][1]);
            FMA2(acc2[i][2], aa, vp[2], acc2[i][2]);
            FMA2(acc2[i][3], aa, vp[3], acc2[i][3]);
        }

        ku = nku; vu = nvu;
    }

    float* sA = sred;
    float* sD = sred + 8 * 2048;
#pragma unroll
    for (int i = 0; i < 8; i++) {
        float a0, a1, a2, a3, a4, a5, a6, a7;
        UNPACKF2(a0, a1, acc2[i][0]); UNPACKF2(a2, a3, acc2[i][1]);
        UNPACKF2(a4, a5, acc2[i][2]); UNPACKF2(a6, a7, acc2[i][3]);
        *(float4*)(sA + wid * 2048 + i * 256 + lane * 8)     = make_float4(a0, a1, a2, a3);
        *(float4*)(sA + wid * 2048 + i * 256 + lane * 8 + 4) = make_float4(a4, a5, a6, a7);
    }
    if (lane == 0) {
#pragma unroll
        for (int i = 0; i < 8; i++) sD[wid * 8 + i] = den[i];
    }
    __syncthreads();

    float* pn = pnum + ((size_t)b * PRED + blockIdx.x) * S * D;
#pragma unroll
    for (int r = 0; r < 8; r++) {
        int idx = tid + r * 256;
        float s = 0.0f;
#pragma unroll
        for (int w = 0; w < 8; w++) s += sA[w * 2048 + idx];
        pn[idx] = s;
    }
    if (tid < 8) {
        float s = 0.0f;
#pragma unroll
        for (int w = 0; w < 8; w++) s += sD[w * 8 + tid];
        pden[(b * PRED + blockIdx.x) * S + tid] = s;
    }
}

__global__ void attn_reduce_kernel(const float* __restrict__ pnum,
                                   const float* __restrict__ pden,
                                   float* __restrict__ upd)
{
    int idx = blockIdx.x * blockDim.x + threadIdx.x;  // over 64*2048
    int b = idx >> 11;
    int i = (idx >> 8) & 7;
    float s = 0.0f, d = 0.0f;
#pragma unroll
    for (int w = 0; w < PRED; w++) {
        s += pnum[((size_t)b * PRED + w) * S * D + (idx & 2047)];
        d += pden[(b * PRED + w) * S + i];
    }
    upd[idx] = s / d;
}

// ---------------- GRU pointwise (torch gate order r,z,n) ---------------------
__global__ void gru_kernel(const float* __restrict__ gx, const float* __restrict__ gh,
                           float* __restrict__ slots)
{
    int idx = blockIdx.x * blockDim.x + threadIdx.x;  // over 512*256
    int row = idx >> 8, d = idx & 255;
    const float* gxr = gx + row * 3 * D;
    const float* ghr = gh + row * 3 * D;
    float xr = gxr[d], xz = gxr[D + d], xn = gxr[2 * D + d];
    float hr = ghr[d], hz = ghr[D + d], hn = ghr[2 * D + d];
    float r = 1.0f / (1.0f + expf(-(xr + hr)));
    float z = 1.0f / (1.0f + expf(-(xz + hz)));
    float nv = tanhf(xn + r * hn);
    float prev = slots[idx];
    slots[idx] = (1.0f - z) * nv + z * prev;
}

// ---------------- host orchestration ----------------------------------------
extern "C" void kernel_launch(void* const* d_in, const int* in_sizes, int n_in,
                              void* d_out, int out_size)
{
    const float* inputs     = (const float*)d_in[0];
    const float* init_slots = (const float*)d_in[1];
    const float* wq   = (const float*)d_in[2];  const float* bq   = (const float*)d_in[3];
    const float* wk   = (const float*)d_in[4];  const float* bk   = (const float*)d_in[5];
    const float* wv   = (const float*)d_in[6];  const float* bv   = (const float*)d_in[7];
    const float* w_ih = (const float*)d_in[8];  const float* b_ih = (const float*)d_in[9];
    const float* w_hh = (const float*)d_in[10]; const float* b_hh = (const float*)d_in[11];
    const float* w1   = (const float*)d_in[12]; const float* b1   = (const float*)d_in[13];
    const float* w2   = (const float*)d_in[14]; const float* b2   = (const float*)d_in[15];
    const float* gin  = (const float*)d_in[16]; const float* bin  = (const float*)d_in[17];
    const float* gsl  = (const float*)d_in[18]; const float* bsl  = (const float*)d_in[19];
    const float* gff  = (const float*)d_in[20]; const float* bff  = (const float*)d_in[21];

    __nv_bfloat16 *xln16, *kv16, *w16;
    float *bias, *slots, *qb, *upd, *hb, *gx, *gh, *pnum, *pden;
    cudaGetSymbolAddress((void**)&xln16, g_xln16);
    cudaGetSymbolAddress((void**)&kv16,  g_kv16);
    cudaGetSymbolAddress((void**)&w16,   g_w16);
    cudaGetSymbolAddress((void**)&bias,  g_bias);
    cudaGetSymbolAddress((void**)&slots, g_slots);
    cudaGetSymbolAddress((void**)&qb,    g_qbuf);
    cudaGetSymbolAddress((void**)&upd,   g_upd);
    cudaGetSymbolAddress((void**)&hb,    g_hbuf);
    cudaGetSymbolAddress((void**)&gx,    g_gx);
    cudaGetSymbolAddress((void**)&gh,    g_gh);
    cudaGetSymbolAddress((void**)&pnum,  g_pnum);
    cudaGetSymbolAddress((void**)&pden,  g_pden);

    cudaFuncSetAttribute(kv_mma_kernel, cudaFuncAttributeMaxDynamicSharedMemorySize, KV_SMEM);
    const int ATTN_SMEM = (8 * 2048 + 64) * sizeof(float);
    cudaFuncSetAttribute(attn_pass_kernel, cudaFuncAttributeMaxDynamicSharedMemorySize, ATTN_SMEM);
    cudaFuncSetAttribute(slotgemm_ln_kernel<0>, cudaFuncAttributeMaxDynamicSharedMemorySize, SG_SMEM);
    cudaFuncSetAttribute(slotgemm_ln_kernel<1>, cudaFuncAttributeMaxDynamicSharedMemorySize, SG_SMEM);

    // prologue
    cudaMemcpyAsync(slots, init_slots, (size_t)ROWS_SLOT * D * sizeof(float),
                    cudaMemcpyDeviceToDevice);
    conv_w_kernel<<<D * D / 256, 256>>>(wk, wv, bk, bv, w16, bias);
    ln_rows_bf16_kernel<<<ROWS_BIG / 8, 256>>>(inputs, xln16, gin, bin);
    kv_mma_kernel<<<dim3(4, ROWS_BIG / BMT), 256, KV_SMEM>>>(xln16, w16, bias, kv16);

    for (int it = 0; it < 3; it++) {
        // q = LN(slots) @ wq^T + bq
        slotgemm_ln_kernel<0><<<dim3(4, 16), 256, SG_SMEM>>>(
            slots, wq, bq, qb, gsl, bsl);
        attn_pass_kernel<<<dim3(PRED, BATCH), 256, ATTN_SMEM>>>(qb, kv16, pnum, pden);
        attn_reduce_kernel<<<(BATCH * S * D) / 256, 256>>>(pnum, pden, upd);
        // gx and gh GEMMs in one launch
        sgemm_kernel<64, 64, 16, 4, 4><<<dim3(24, 8), 256>>>(
            upd, w_ih, b_ih, gx, ROWS_SLOT, 3 * D, D, 0, 0,
            slots, w_hh, b_hh, gh, 12);
        gru_kernel<<<(ROWS_SLOT * D) / 256, 256>>>(gx, gh, slots);
        // h = relu(LN(slots) @ w1^T + b1)
        slotgemm_ln_kernel<1><<<dim3(4, 16), 256, SG_SMEM>>>(
            slots, w1, b1, hb, gff, bff);
        // slots += h @ w2^T + b2
        sgemm_kernel<64, 64, 16, 4, 4><<<dim3(4, 8), 256>>>(
            hb, w2, b2, slots, ROWS_SLOT, D, D, 0, 1,
            nullptr, nullptr, nullptr, nullptr, 1 << 20);
    }

    cudaMemcpyAsync(d_out, slots, (size_t)ROWS_SLOT * D * sizeof(float),
                    cudaMemcpyDeviceToDevice);
}